// round 1
// baseline (speedup 1.0000x reference)
#include <cuda_runtime.h>
#include <math.h>

#define TT  8
#define NN  100000
#define HH  128
#define HIN 64
#define NODES_PER_CTA 32

// ---------------- device scratch (no allocations allowed) ----------------
__device__ float g_WT[3*HH*HH];      // combined qkv weights, [mat][c][j]: q[j] = sum_c A[c]*WT[c*H+j]
__device__ float g_bias[3*TT*HH];    // [mat][t][j] = (proj_b + pe[t]) @ w^T
__device__ float g_fcT[HH*HH];       // fcT[c][j] = fc_w[j][c]
__device__ float g_resT[HIN*HH];     // resT[c][j] = res_w[j][c]
__device__ float g_alpha[1];
__device__ float g_attn[(size_t)TT*NN*HH];   // 409.6 MB attention output scratch

// ---------------- kernel 0: fold proj into qkv, transpose weights ----------------
__global__ void prep_kernel(const float* __restrict__ proj_w, const float* __restrict__ proj_b,
                            const float* __restrict__ q_w, const float* __restrict__ k_w,
                            const float* __restrict__ v_w, const float* __restrict__ fc_w,
                            const float* __restrict__ res_w, const float* __restrict__ res_alpha)
{
    int idx = blockIdx.x * blockDim.x + threadIdx.x;
    const int NW = 3*HH*HH;                 // 49152
    const int NB = NW + 3*TT*HH;            // +3072
    const int NF = NB + HH*HH;              // +16384
    const int NR = NF + HIN*HH;             // +8192
    if (idx < NW) {
        int mat = idx / (HH*HH); int rem = idx % (HH*HH);
        int c = rem / HH, j = rem % HH;
        const float* w = (mat==0) ? q_w : ((mat==1) ? k_w : v_w);
        double s = 0.0;
        for (int m = 0; m < HH; m++) s += (double)w[j*HH+m] * (double)proj_w[m*HH+c];
        g_WT[idx] = (float)s;
    } else if (idx < NB) {
        int r = idx - NW;
        int mat = r / (TT*HH); int rr = r % (TT*HH);
        int t = rr / HH, j = rr % HH;
        const float* w = (mat==0) ? q_w : ((mat==1) ? k_w : v_w);
        double s = 0.0;
        for (int m = 0; m < HH; m++) {
            double div = exp((double)(m & ~1) * (-log(100000.0)) / (double)HH);
            double ph  = (double)(t + 1) * div;
            float pe   = (float)((m & 1) ? cos(ph) : sin(ph));   // numpy stores pe as f32
            s += ((double)proj_b[m] + (double)pe) * (double)w[j*HH+m];
        }
        g_bias[r] = (float)s;
    } else if (idx < NF) {
        int r = idx - NB;
        int c = r / HH, j = r % HH;
        g_fcT[r] = fc_w[j*HH + c];
    } else if (idx < NR) {
        int r = idx - NF;
        int c = r / HH, j = r % HH;
        g_resT[r] = res_w[j*HIN + c];
    } else if (idx == NR) {
        g_alpha[0] = 1.0f / (1.0f + expf(-res_alpha[0]));
    }
}

// ---------------- kernel 1: qkv + attention ----------------
// smem floats: WT 49152 | bias 3072 | A 1024 | qkv 3072 | S 64  => 56384 floats = 225536 B
#define K1_SMEM_BYTES (56384*4)

__global__ __launch_bounds__(256, 1) void attn_kernel(const float* __restrict__ inter)
{
    extern __shared__ float sm[];
    float* WT   = sm;
    float* bias = sm + 49152;
    float* As   = sm + 52224;
    float* qkv  = sm + 53248;
    float* S    = sm + 56320;

    int tid = threadIdx.x;
    int warp = tid >> 5, lane = tid & 31;

    for (int i = tid; i < 3*HH*HH; i += 256) WT[i] = g_WT[i];
    for (int i = tid; i < 3*TT*HH; i += 256) bias[i] = g_bias[i];

    for (int it = 0; it < NODES_PER_CTA; it++) {
        int n = blockIdx.x * NODES_PER_CTA + it;
        __syncthreads();   // prev iter fully consumed qkv/S; weights ready (iter 0)

        // phase 1: stage A[8][128] (warp w loads row t=w)
        {
            float4 v = *(const float4*)(inter + ((size_t)warp*NN + n)*HH + lane*4);
            *(float4*)(As + warp*HH + lane*4) = v;
        }
        __syncthreads();

        // phase 2: q,k,v = A @ WT + bias   (192 threads: mat x 2 t-halves x 32 j-quads)
        if (tid < 192) {
            int mat = tid / 64;
            int r   = tid & 63;
            int t0  = (r >> 5) * 4;
            int j0  = (r & 31) * 4;
            const float* W = WT + mat*HH*HH;
            const float* B = bias + mat*TT*HH;
            float acc[4][4];
            #pragma unroll
            for (int ti = 0; ti < 4; ti++)
                #pragma unroll
                for (int ji = 0; ji < 4; ji++)
                    acc[ti][ji] = B[(t0+ti)*HH + j0 + ji];
            #pragma unroll 4
            for (int c = 0; c < HH; c += 4) {
                float4 a[4];
                #pragma unroll
                for (int ti = 0; ti < 4; ti++) a[ti] = *(const float4*)(As + (t0+ti)*HH + c);
                #pragma unroll
                for (int ci = 0; ci < 4; ci++) {
                    float4 w = *(const float4*)(W + (c+ci)*HH + j0);
                    #pragma unroll
                    for (int ti = 0; ti < 4; ti++) {
                        float av = (&a[ti].x)[ci];
                        acc[ti][0] += av * w.x;
                        acc[ti][1] += av * w.y;
                        acc[ti][2] += av * w.z;
                        acc[ti][3] += av * w.w;
                    }
                }
            }
            float* dst = qkv + mat*TT*HH;
            #pragma unroll
            for (int ti = 0; ti < 4; ti++) {
                float4 o = { acc[ti][0], acc[ti][1], acc[ti][2], acc[ti][3] };
                *(float4*)(dst + (t0+ti)*HH + j0) = o;
            }
        }
        __syncthreads();

        // phase 3: scores row t=warp, softmax; phase 4: attn = S @ v
        {
            int t = warp;
            const float* q = qkv;
            const float* k = qkv + TT*HH;
            float qc[4];
            #pragma unroll
            for (int u = 0; u < 4; u++) qc[u] = q[t*HH + lane + 32*u];
            #pragma unroll
            for (int s = 0; s < TT; s++) {
                float p = 0.f;
                #pragma unroll
                for (int u = 0; u < 4; u++) p += qc[u] * k[s*HH + lane + 32*u];
                #pragma unroll
                for (int off = 16; off > 0; off >>= 1) p += __shfl_xor_sync(0xffffffffu, p, off);
                if (lane == 0) S[t*TT + s] = p;
            }
            __syncwarp();
            if (lane == 0) {
                float mx = S[t*TT];
                #pragma unroll
                for (int s = 1; s < TT; s++) mx = fmaxf(mx, S[t*TT + s]);
                float e[TT]; float sum = 0.f;
                #pragma unroll
                for (int s = 0; s < TT; s++) { e[s] = expf(S[t*TT + s] - mx); sum += e[s]; }
                float inv = 1.f / sum;
                #pragma unroll
                for (int s = 0; s < TT; s++) S[t*TT + s] = e[s] * inv;
            }
            __syncwarp();
            const float* v = qkv + 2*TT*HH;
            int j0 = lane * 4;
            float4 o = {0.f, 0.f, 0.f, 0.f};
            #pragma unroll
            for (int s = 0; s < TT; s++) {
                float sc = S[t*TT + s];
                float4 v4 = *(const float4*)(v + s*HH + j0);
                o.x += sc*v4.x; o.y += sc*v4.y; o.z += sc*v4.z; o.w += sc*v4.w;
            }
            *(float4*)(g_attn + ((size_t)t*NN + n)*HH + j0) = o;
        }
    }
}

// ---------------- kernel 2: fc + relu + gated residual + LayerNorm ----------------
// smem floats: fcT 16384 | resT 8192 | fcb 128 | resb 128 | lng 128 | lnb 128 | rowbuf 1024 | xbuf 512 | alpha 1 = 26625
#define K2_SMEM_BYTES (26625*4)

__global__ __launch_bounds__(256, 2) void out_kernel(const float* __restrict__ x,
        const float* __restrict__ fc_b, const float* __restrict__ res_b,
        const float* __restrict__ ln_g, const float* __restrict__ ln_b,
        float* __restrict__ out)
{
    extern __shared__ float sm[];
    float* fcT    = sm;
    float* resT   = sm + 16384;
    float* fcb    = sm + 24576;
    float* resb   = sm + 24704;
    float* lng    = sm + 24832;
    float* lnb    = sm + 24960;
    float* rowbuf = sm + 25088;   // 8 warps x 128
    float* xbuf   = sm + 26112;   // 8 warps x 64

    int tid = threadIdx.x;
    for (int i = tid; i < HH*HH;  i += 256) fcT[i]  = g_fcT[i];
    for (int i = tid; i < HIN*HH; i += 256) resT[i] = g_resT[i];
    if (tid < 128) { fcb[tid] = fc_b[tid]; resb[tid] = res_b[tid]; lng[tid] = ln_g[tid]; lnb[tid] = ln_b[tid]; }
    if (tid == 0) sm[26624] = g_alpha[0];
    __syncthreads();
    float alpha = sm[26624];
    float beta  = 1.f - alpha;

    int warp = tid >> 5, lane = tid & 31;
    int j0 = lane * 4;
    float* rb = rowbuf + warp*HH;
    float* xb = xbuf + warp*HIN;

    const long totalRows = (long)TT*NN;
    for (long row = (long)blockIdx.x*8 + warp; row < totalRows; row += (long)gridDim.x*8) {
        float4 a4 = *(const float4*)(g_attn + row*HH + j0);
        *(float4*)(rb + j0) = a4;
        if (lane < 16) {
            float4 xv = *(const float4*)(x + row*HIN + lane*4);
            *(float4*)(xb + lane*4) = xv;
        }
        __syncwarp();

        float acc[4];
        #pragma unroll
        for (int i = 0; i < 4; i++) acc[i] = fcb[j0 + i];
        #pragma unroll 4
        for (int c = 0; c < HH; c += 4) {
            float4 av = *(const float4*)(rb + c);
            #pragma unroll
            for (int ci = 0; ci < 4; ci++) {
                float4 w = *(const float4*)(fcT + (c+ci)*HH + j0);
                float a = (&av.x)[ci];
                acc[0] += a*w.x; acc[1] += a*w.y; acc[2] += a*w.z; acc[3] += a*w.w;
            }
        }
        float r[4];
        #pragma unroll
        for (int i = 0; i < 4; i++) r[i] = resb[j0 + i];
        #pragma unroll 4
        for (int c = 0; c < HIN; c += 4) {
            float4 xv = *(const float4*)(xb + c);
            #pragma unroll
            for (int ci = 0; ci < 4; ci++) {
                float4 w = *(const float4*)(resT + (c+ci)*HH + j0);
                float a = (&xv.x)[ci];
                r[0] += a*w.x; r[1] += a*w.y; r[2] += a*w.z; r[3] += a*w.w;
            }
        }
        float o[4]; float s = 0.f, s2 = 0.f;
        #pragma unroll
        for (int i = 0; i < 4; i++) {
            float h = fmaxf(acc[i], 0.f);
            o[i] = h*alpha + r[i]*beta;
            s  += o[i];
            s2 += o[i]*o[i];
        }
        #pragma unroll
        for (int off = 16; off > 0; off >>= 1) {
            s  += __shfl_xor_sync(0xffffffffu, s,  off);
            s2 += __shfl_xor_sync(0xffffffffu, s2, off);
        }
        float mean = s * (1.f/HH);
        float var  = s2 * (1.f/HH) - mean*mean;
        float inv  = rsqrtf(var + 1e-5f);
        float4 ov;
        #pragma unroll
        for (int i = 0; i < 4; i++) (&ov.x)[i] = (o[i] - mean)*inv*lng[j0+i] + lnb[j0+i];
        *(float4*)(out + row*HH + j0) = ov;
        __syncwarp();
    }
}

// ---------------- launch ----------------
extern "C" void kernel_launch(void* const* d_in, const int* in_sizes, int n_in,
                              void* d_out, int out_size)
{
    const float* inter     = (const float*)d_in[0];
    const float* x         = (const float*)d_in[1];
    const float* proj_w    = (const float*)d_in[2];
    const float* proj_b    = (const float*)d_in[3];
    const float* q_w       = (const float*)d_in[4];
    const float* k_w       = (const float*)d_in[5];
    const float* v_w       = (const float*)d_in[6];
    const float* fc_w      = (const float*)d_in[7];
    const float* fc_b      = (const float*)d_in[8];
    const float* res_w     = (const float*)d_in[9];
    const float* res_b     = (const float*)d_in[10];
    const float* res_alpha = (const float*)d_in[11];
    const float* ln_g      = (const float*)d_in[12];
    const float* ln_b      = (const float*)d_in[13];
    float* out = (float*)d_out;

    cudaFuncSetAttribute(attn_kernel, cudaFuncAttributeMaxDynamicSharedMemorySize, K1_SMEM_BYTES);
    cudaFuncSetAttribute(out_kernel,  cudaFuncAttributeMaxDynamicSharedMemorySize, K2_SMEM_BYTES);

    prep_kernel<<<301, 256>>>(proj_w, proj_b, q_w, k_w, v_w, fc_w, res_w, res_alpha);
    attn_kernel<<<NN / NODES_PER_CTA, 256, K1_SMEM_BYTES>>>(inter);
    out_kernel<<<2960, 256, K2_SMEM_BYTES>>>(x, fc_b, res_b, ln_g, ln_b, out);
}